// round 1
// baseline (speedup 1.0000x reference)
#include <cuda_runtime.h>
#include <cuda_bf16.h>
#include <math_constants.h>

// Problem constants
#define Bb 2
#define SS 2048
#define DD 1024
#define HH 16
#define DKk 64
#define MM (Bb * SS)   // 4096 rows for all GEMMs

// ---------------------------------------------------------------------------
// Scratch (device globals — no allocations allowed)
// ---------------------------------------------------------------------------
__device__ float g_inter[(size_t)Bb * SS * DD];   // query @ Wp
__device__ float g_Q[(size_t)Bb * SS * DD];
__device__ float g_K[(size_t)Bb * SS * DD];
__device__ float g_V[(size_t)Bb * SS * DD];
__device__ float g_ctx[(size_t)Bb * SS * DD];
__device__ float g_rl[Bb * (SS - 1)];
__device__ float g_rr[Bb * (SS - 1)];
__device__ float g_gate[Bb];
__device__ int   g_skip;   // 1 => gate[0]==0 && gate[1]==0 => output == bo broadcast

// ---------------------------------------------------------------------------
// Generic 128x128x8 fp32 tiled GEMM, hardcoded M=4096, N=1024, K=1024.
//   C = A[4096,1024] @ Bm[1024,1024] (+ bias per column, optional)
// mode: 0 = always run (gate GEMM)
//       1 = early-exit if g_skip (QKV projections)
//       2 = if g_skip, write bias broadcast instead (output projection)
// ---------------------------------------------------------------------------
#define GK 1024
#define GN 1024

__global__ void __launch_bounds__(256) sgemm128(
    const float* __restrict__ A, const float* __restrict__ Bm,
    const float* __restrict__ bias, float* __restrict__ C, int mode)
{
    const int n0 = blockIdx.x * 128;
    const int m0 = blockIdx.y * 128;
    const int tid = threadIdx.x;

    if (mode != 0 && g_skip) {
        if (mode == 2) {
            // out = bo broadcast over rows (exact reference result when gate == 0)
            for (int idx = tid; idx < 128 * 32; idx += 256) {
                int r  = idx >> 5;        // 0..127
                int c4 = idx & 31;        // 0..31 float4 within 128 cols
                float4 bv = ((const float4*)(bias + n0))[c4];
                ((float4*)(C + (size_t)(m0 + r) * GN + n0))[c4] = bv;
            }
        }
        return;
    }

    __shared__ float As[8][128];
    __shared__ float Bs[8][128];

    float acc[8][8];
#pragma unroll
    for (int i = 0; i < 8; i++)
#pragma unroll
        for (int j = 0; j < 8; j++) acc[i][j] = 0.f;

    const int ty = tid >> 4;        // 0..15
    const int tx = tid & 15;        // 0..15
    const int arow = tid >> 1;      // 0..127
    const int acol = (tid & 1) * 4; // 0 or 4
    const int brow = tid >> 5;      // 0..7
    const int bcol = (tid & 31) * 4;

    for (int k0 = 0; k0 < GK; k0 += 8) {
        float4 av = *(const float4*)(A + (size_t)(m0 + arow) * GK + k0 + acol);
        float4 bv = *(const float4*)(Bm + (size_t)(k0 + brow) * GN + n0 + bcol);
        As[acol + 0][arow] = av.x;
        As[acol + 1][arow] = av.y;
        As[acol + 2][arow] = av.z;
        As[acol + 3][arow] = av.w;
        *(float4*)&Bs[brow][bcol] = bv;
        __syncthreads();
#pragma unroll
        for (int kk = 0; kk < 8; kk++) {
            float a[8], bb[8];
            float4 a0 = *(const float4*)&As[kk][ty * 8];
            float4 a1 = *(const float4*)&As[kk][ty * 8 + 4];
            float4 b0 = *(const float4*)&Bs[kk][tx * 8];
            float4 b1 = *(const float4*)&Bs[kk][tx * 8 + 4];
            a[0]=a0.x; a[1]=a0.y; a[2]=a0.z; a[3]=a0.w;
            a[4]=a1.x; a[5]=a1.y; a[6]=a1.z; a[7]=a1.w;
            bb[0]=b0.x; bb[1]=b0.y; bb[2]=b0.z; bb[3]=b0.w;
            bb[4]=b1.x; bb[5]=b1.y; bb[6]=b1.z; bb[7]=b1.w;
#pragma unroll
            for (int i = 0; i < 8; i++)
#pragma unroll
                for (int j = 0; j < 8; j++) acc[i][j] += a[i] * bb[j];
        }
        __syncthreads();
    }

#pragma unroll
    for (int i = 0; i < 8; i++) {
        int m = m0 + ty * 8 + i;
#pragma unroll
        for (int j = 0; j < 8; j += 4) {
            int n = n0 + tx * 8 + j;
            float4 v;
            v.x = acc[i][j + 0] + (bias ? bias[n + 0] : 0.f);
            v.y = acc[i][j + 1] + (bias ? bias[n + 1] : 0.f);
            v.z = acc[i][j + 2] + (bias ? bias[n + 2] : 0.f);
            v.w = acc[i][j + 3] + (bias ? bias[n + 3] : 0.f);
            *(float4*)(C + (size_t)m * GN + n) = v;
        }
    }
}

// ---------------------------------------------------------------------------
// r_left[b,i] = inter[b,i+1] . key[b,i] ; r_right[b,i] = inter[b,i] . key[b,i+1]
// i in [0, S-2]; one block per (b,i)
// ---------------------------------------------------------------------------
__global__ void __launch_bounds__(256) compute_r_kernel(const float* __restrict__ key)
{
    const int bid = blockIdx.x;               // b*(S-1)+i
    const int b = bid / (SS - 1);
    const int i = bid % (SS - 1);
    const float* it0 = g_inter + ((size_t)b * SS + i) * DD;
    const float* it1 = it0 + DD;
    const float* k0  = key + ((size_t)b * SS + i) * DD;
    const float* k1  = k0 + DD;

    float srl = 0.f, srr = 0.f;
    for (int d = threadIdx.x; d < DD; d += 256) {
        srl += it1[d] * k0[d];
        srr += it0[d] * k1[d];
    }
#pragma unroll
    for (int o = 16; o > 0; o >>= 1) {
        srl += __shfl_xor_sync(0xffffffffu, srl, o);
        srr += __shfl_xor_sync(0xffffffffu, srr, o);
    }
    __shared__ float sl[8], sr[8];
    int w = threadIdx.x >> 5, lane = threadIdx.x & 31;
    if (lane == 0) { sl[w] = srl; sr[w] = srr; }
    __syncthreads();
    if (threadIdx.x == 0) {
        float a = 0.f, c = 0.f;
#pragma unroll
        for (int j = 0; j < 8; j++) { a += sl[j]; c += sr[j]; }
        g_rl[bid] = a;
        g_rr[bid] = c;
    }
}

// ---------------------------------------------------------------------------
// Gate: softmax of (rl[t], rr[t+1]) pairs, Pi chain, log-sum, exp. Sets g_skip.
// ---------------------------------------------------------------------------
__global__ void __launch_bounds__(256) gate_kernel()
{
    __shared__ float red[256];
    for (int b = 0; b < Bb; b++) {
        const float* rl = g_rl + b * (SS - 1);
        const float* rr = g_rr + b * (SS - 1);
        float p = 0.f;
        // Pi_t uses pr[t,1]=sigmoid(rr[t+1]-rl[t]) and pr[t+1,0]=sigmoid(rl[t+1]-rr[t+2])
        for (int t = threadIdx.x; t <= SS - 4; t += 256) {
            float pr1 = 1.f / (1.f + expf(rl[t]     - rr[t + 1]));
            float pr0 = 1.f / (1.f + expf(rr[t + 2] - rl[t + 1]));
            float Pi  = sqrtf(pr1 * pr0 + 1e-9f);
            p += logf(Pi + 1e-8f);
        }
        red[threadIdx.x] = p;
        __syncthreads();
        for (int st = 128; st > 0; st >>= 1) {
            if (threadIdx.x < st) red[threadIdx.x] += red[threadIdx.x + st];
            __syncthreads();
        }
        if (threadIdx.x == 0) g_gate[b] = expf(red[0]);
        __syncthreads();
    }
    if (threadIdx.x == 0)
        g_skip = (g_gate[0] == 0.f && g_gate[1] == 0.f) ? 1 : 0;
}

// ---------------------------------------------------------------------------
// Flash-style causal attention (safety path; only runs if gate != 0).
// ctx[b,s,h*64..] = gate[b] * softmax(Q K^T / 8, causal) V
// grid (S/128, B*H), 128 threads = one q row each.
// ---------------------------------------------------------------------------
#define KT 64
__global__ void __launch_bounds__(128) attention_kernel()
{
    if (g_skip) return;
    const int qt = blockIdx.x;
    const int bh = blockIdx.y;
    const int b = bh / HH, h = bh % HH;
    const int tid = threadIdx.x;
    const int q = qt * 128 + tid;

    const float* Qp = g_Q + ((size_t)b * SS + q) * DD + h * DKk;
    float qreg[DKk];
#pragma unroll
    for (int d = 0; d < DKk; d++) qreg[d] = Qp[d];

    float m = -CUDART_INF_F, l = 0.f;
    float accv[DKk];
#pragma unroll
    for (int d = 0; d < DKk; d++) accv[d] = 0.f;

    __shared__ float Ks[KT][DKk];
    __shared__ float Vs[KT][DKk];

    const int kmax = qt * 128 + 128;
    for (int k0 = 0; k0 < kmax; k0 += KT) {
        __syncthreads();
        for (int idx = tid; idx < KT * (DKk / 4); idx += 128) {
            int rr = idx / (DKk / 4), cc = idx % (DKk / 4);
            const float4* kp = (const float4*)(g_K + ((size_t)b * SS + k0 + rr) * DD + h * DKk) + cc;
            const float4* vp = (const float4*)(g_V + ((size_t)b * SS + k0 + rr) * DD + h * DKk) + cc;
            ((float4*)&Ks[rr][0])[cc] = *kp;
            ((float4*)&Vs[rr][0])[cc] = *vp;
        }
        __syncthreads();
        int jend = q - k0 + 1;
        if (jend > KT) jend = KT;
        for (int j = 0; j < jend; j++) {
            float s = 0.f;
#pragma unroll
            for (int d = 0; d < DKk; d++) s += qreg[d] * Ks[j][d];
            s *= 0.125f;  // 1/sqrt(64)
            float mn = fmaxf(m, s);
            float corr = __expf(m - mn);
            float pexp = __expf(s - mn);
            l = l * corr + pexp;
#pragma unroll
            for (int d = 0; d < DKk; d++) accv[d] = accv[d] * corr + pexp * Vs[j][d];
            m = mn;
        }
    }
    float inv = g_gate[b] / l;
    float* cp = g_ctx + ((size_t)b * SS + q) * DD + h * DKk;
#pragma unroll
    for (int d = 0; d < DKk; d++) cp[d] = accv[d] * inv;
}

// ---------------------------------------------------------------------------
// Launch
// ---------------------------------------------------------------------------
extern "C" void kernel_launch(void* const* d_in, const int* in_sizes, int n_in,
                              void* d_out, int out_size)
{
    const float* query = (const float*)d_in[0];
    const float* key   = (const float*)d_in[1];
    const float* value = (const float*)d_in[2];
    // d_in[3] = causal_mask (fixed tril, handled analytically)
    const float* Wq = (const float*)d_in[4];
    const float* bq = (const float*)d_in[5];
    const float* Wk = (const float*)d_in[6];
    const float* bk = (const float*)d_in[7];
    const float* Wv = (const float*)d_in[8];
    const float* bv = (const float*)d_in[9];
    const float* Wo = (const float*)d_in[10];
    const float* bo = (const float*)d_in[11];
    const float* Wp = (const float*)d_in[12];
    float* out = (float*)d_out;

    void *p_inter, *p_Q, *p_K, *p_V, *p_ctx;
    cudaGetSymbolAddress(&p_inter, g_inter);
    cudaGetSymbolAddress(&p_Q, g_Q);
    cudaGetSymbolAddress(&p_K, g_K);
    cudaGetSymbolAddress(&p_V, g_V);
    cudaGetSymbolAddress(&p_ctx, g_ctx);

    dim3 gemm_grid(GN / 128, MM / 128);  // (8, 32)

    // 1) inter = query @ Wp (always)
    sgemm128<<<gemm_grid, 256>>>(query, Wp, nullptr, (float*)p_inter, 0);
    // 2) off-diagonal dots
    compute_r_kernel<<<Bb * (SS - 1), 256>>>(key);
    // 3) gate + skip flag
    gate_kernel<<<1, 256>>>();
    // 4) QKV projections (skip if gate == 0)
    sgemm128<<<gemm_grid, 256>>>(query, Wq, bq, (float*)p_Q, 1);
    sgemm128<<<gemm_grid, 256>>>(key,   Wk, bk, (float*)p_K, 1);
    sgemm128<<<gemm_grid, 256>>>(value, Wv, bv, (float*)p_V, 1);
    // 5) causal attention * gate (skip if gate == 0)
    attention_kernel<<<dim3(SS / 128, Bb * HH), 128>>>();
    // 6) out = ctx @ Wo + bo, or bo broadcast on skip
    sgemm128<<<gemm_grid, 256>>>((const float*)p_ctx, Wo, bo, out, 2);
}

// round 5
// speedup vs baseline: 3.7909x; 3.7909x over previous
#include <cuda_runtime.h>
#include <cuda_bf16.h>
#include <math_constants.h>
#include <cstdint>

// Problem constants
#define Bb 2
#define SS 2048
#define DD 1024
#define HH 16
#define DKk 64
#define MM (Bb * SS)   // 4096 rows

// ---------------------------------------------------------------------------
// Scratch (device globals — no allocations allowed)
// ---------------------------------------------------------------------------
__device__ __nv_bfloat16 g_qbf[(size_t)MM * DD];      // query in bf16 (A, row-major)
__device__ __nv_bfloat16 g_wbf[(size_t)DD * DD];      // Wp in bf16 (B, row-major [k][n])
__device__ float g_Q[(size_t)Bb * SS * DD];
__device__ float g_K[(size_t)Bb * SS * DD];
__device__ float g_V[(size_t)Bb * SS * DD];
__device__ float g_ctx[(size_t)Bb * SS * DD];
__device__ float g_rl[Bb * (SS - 1)];
__device__ float g_rr[Bb * (SS - 1)];
__device__ float g_gate[Bb];
__device__ int   g_skip;

// ---------------------------------------------------------------------------
// mma.sync helpers (sm_80+ path — works on base sm_103 target)
// ---------------------------------------------------------------------------
__device__ __forceinline__ uint32_t smem_u32(const void* p) {
    uint32_t a;
    asm("{ .reg .u64 t; cvta.to.shared.u64 t, %1; cvt.u32.u64 %0, t; }" : "=r"(a) : "l"(p));
    return a;
}
__device__ __forceinline__ void cp16(uint32_t dst, const void* src) {
    asm volatile("cp.async.cg.shared.global [%0], [%1], 16;" :: "r"(dst), "l"(src));
}
__device__ __forceinline__ void ldm_x4(uint32_t& a0, uint32_t& a1, uint32_t& a2, uint32_t& a3,
                                       uint32_t addr) {
    asm volatile("ldmatrix.sync.aligned.m8n8.x4.shared.b16 {%0,%1,%2,%3}, [%4];"
                 : "=r"(a0), "=r"(a1), "=r"(a2), "=r"(a3) : "r"(addr));
}
__device__ __forceinline__ void ldm_x2t(uint32_t& b0, uint32_t& b1, uint32_t addr) {
    asm volatile("ldmatrix.sync.aligned.m8n8.x2.trans.shared.b16 {%0,%1}, [%2];"
                 : "=r"(b0), "=r"(b1) : "r"(addr));
}
__device__ __forceinline__ void mma16816(float* c, uint32_t a0, uint32_t a1, uint32_t a2,
                                         uint32_t a3, uint32_t b0, uint32_t b1) {
    asm volatile(
        "mma.sync.aligned.m16n8k16.row.col.f32.bf16.bf16.f32 "
        "{%0,%1,%2,%3}, {%4,%5,%6,%7}, {%8,%9}, {%0,%1,%2,%3};"
        : "+f"(c[0]), "+f"(c[1]), "+f"(c[2]), "+f"(c[3])
        : "r"(a0), "r"(a1), "r"(a2), "r"(a3), "r"(b0), "r"(b1));
}

// ---------------------------------------------------------------------------
// Gate GEMM (bf16 HMMA, 128x128 CTA tile, K-chunk 64, cp.async double buffer)
//   C[m,n] = sum_k q_bf16[m,k] * Wp_bf16[k,n]   (C never materialized)
// Fused epilogue:
//   r_left[b,s-1]  += C[m,:] . key[m-1,:]   (s>=1)
//   r_right[b,s]   += C[m,:] . key[m+1,:]   (s<=S-2)
// ---------------------------------------------------------------------------
#define SMEM_GEMM (2 * 32768)   // double-buffered: A 16KB + B 16KB per buffer

__global__ void __launch_bounds__(256) gate_gemm_mma(const float* __restrict__ key)
{
    extern __shared__ __align__(128) char sm[];
    const uint32_t sbase = smem_u32(sm);
    const int tid = threadIdx.x;
    const int lane = tid & 31;
    const int wid = tid >> 5;
    const int wm = wid >> 2;         // 0..1 : 64-row warp block
    const int wn = wid & 3;          // 0..3 : 32-col warp block
    const int n0 = blockIdx.x * 128;
    const int m0 = blockIdx.y * 128;

    float acc[4][4][4];
#pragma unroll
    for (int mi = 0; mi < 4; mi++)
#pragma unroll
        for (int ni = 0; ni < 4; ni++)
#pragma unroll
            for (int j = 0; j < 4; j++) acc[mi][ni][j] = 0.f;

    // chunk loader: A 128x64 bf16 (128B rows, xor-swizzled 16B chunks),
    //               B 64x128 bf16 (256B rows, xor-swizzled within 128B half)
    auto load_chunk = [&](int kc, int buf) {
        const uint32_t base = sbase + buf * 32768u;
#pragma unroll
        for (int p = 0; p < 4; p++) {
            int ra = (tid >> 3) + p * 32, ca = tid & 7;
            const char* src = (const char*)g_qbf +
                ((size_t)(m0 + ra) * DD + kc * 64 + ca * 8) * 2;
            cp16(base + ra * 128 + ((ca ^ (ra & 7)) << 4), src);
        }
#pragma unroll
        for (int p = 0; p < 4; p++) {
            int kb = (tid >> 4) + p * 16, cb = tid & 15;
            const char* src = (const char*)g_wbf +
                ((size_t)(kc * 64 + kb) * DD + n0 + cb * 8) * 2;
            uint32_t swc = (cb & 8) | ((cb ^ (kb & 7)) & 7);
            cp16(base + 16384 + kb * 256 + swc * 16, src);
        }
        asm volatile("cp.async.commit_group;" ::: "memory");
    };

    load_chunk(0, 0);
    for (int kc = 0; kc < 16; kc++) {
        const int buf = kc & 1;
        if (kc + 1 < 16) {
            load_chunk(kc + 1, buf ^ 1);
            asm volatile("cp.async.wait_group 1;" ::: "memory");
        } else {
            asm volatile("cp.async.wait_group 0;" ::: "memory");
        }
        __syncthreads();

        const uint32_t abase = sbase + buf * 32768u;
        const uint32_t bbase = abase + 16384u;
#pragma unroll
        for (int kk = 0; kk < 4; kk++) {
            uint32_t a[4][4];
#pragma unroll
            for (int mi = 0; mi < 4; mi++) {
                int r = wm * 64 + mi * 16 + (lane & 7) + ((lane >> 3) & 1) * 8;
                int c = kk * 2 + (lane >> 4);
                ldm_x4(a[mi][0], a[mi][1], a[mi][2], a[mi][3],
                       abase + r * 128 + ((c ^ (r & 7)) << 4));
            }
            uint32_t b[4][2];
#pragma unroll
            for (int ni = 0; ni < 4; ni++) {
                int k = kk * 16 + (lane & 15);
                int cc = wn * 4 + ni;
                uint32_t swc = (cc & 8) | ((cc ^ (k & 7)) & 7);
                ldm_x2t(b[ni][0], b[ni][1], bbase + k * 256 + swc * 16);
            }
#pragma unroll
            for (int mi = 0; mi < 4; mi++)
#pragma unroll
                for (int ni = 0; ni < 4; ni++)
                    mma16816(acc[mi][ni], a[mi][0], a[mi][1], a[mi][2], a[mi][3],
                             b[ni][0], b[ni][1]);
        }
        __syncthreads();
    }

    // Fused epilogue: r-dots straight off the fragments.
    // C frag map (m16n8k16): c0,c1 -> row q; c2,c3 -> row q+8; cols tq*2, tq*2+1.
    const int q = lane >> 2, tq = lane & 3;
#pragma unroll
    for (int mi = 0; mi < 4; mi++) {
        const int rbase = m0 + wm * 64 + mi * 16;
#pragma unroll
        for (int half = 0; half < 2; half++) {
            const int m = rbase + q + half * 8;
            const int s = m & (SS - 1);
            const int bI = m >> 11;
            const bool hasL = (s >= 1);
            const bool hasR = (s <= SS - 2);
            const float* kl = key + (size_t)(m - 1) * DD + n0 + wn * 32;
            const float* kr = key + (size_t)(m + 1) * DD + n0 + wn * 32;
            float dL = 0.f, dR = 0.f;
#pragma unroll
            for (int ni = 0; ni < 4; ni++) {
                float c0 = acc[mi][ni][half * 2 + 0];
                float c1 = acc[mi][ni][half * 2 + 1];
                int col = ni * 8 + tq * 2;
                if (hasL) { dL += c0 * kl[col] + c1 * kl[col + 1]; }
                if (hasR) { dR += c0 * kr[col] + c1 * kr[col + 1]; }
            }
            dL += __shfl_xor_sync(0xffffffffu, dL, 1);
            dL += __shfl_xor_sync(0xffffffffu, dL, 2);
            dR += __shfl_xor_sync(0xffffffffu, dR, 1);
            dR += __shfl_xor_sync(0xffffffffu, dR, 2);
            if (tq == 0) {
                if (hasL) atomicAdd(&g_rl[bI * (SS - 1) + (s - 1)], dL);
                if (hasR) atomicAdd(&g_rr[bI * (SS - 1) + s], dR);
            }
        }
    }
}

// ---------------------------------------------------------------------------
// Conversions
// ---------------------------------------------------------------------------
__global__ void __launch_bounds__(256) cvt_q_bf16(const float4* __restrict__ in,
                                                 __nv_bfloat162* __restrict__ out2)
{
    int i = blockIdx.x * 256 + threadIdx.x;   // i < MM*DD/4 = 1M
    float4 v = in[i];
    out2[2 * i]     = __floats2bfloat162_rn(v.x, v.y);
    out2[2 * i + 1] = __floats2bfloat162_rn(v.z, v.w);
}

__global__ void __launch_bounds__(256) cvt_w_bf16(const float4* __restrict__ in,
                                                  __nv_bfloat162* __restrict__ out2)
{
    int i = blockIdx.x * 256 + threadIdx.x;   // i < DD*DD/4 = 256K
    float4 v = in[i];
    out2[2 * i]     = __floats2bfloat162_rn(v.x, v.y);
    out2[2 * i + 1] = __floats2bfloat162_rn(v.z, v.w);
}

__global__ void __launch_bounds__(256) zero_r_kernel()
{
    int i = blockIdx.x * 256 + threadIdx.x;
    if (i < Bb * (SS - 1)) { g_rl[i] = 0.f; g_rr[i] = 0.f; }
}

// ---------------------------------------------------------------------------
// Gate: softmax pairs -> Pi chain -> log-sum -> exp. Sets g_skip.
// ---------------------------------------------------------------------------
__global__ void __launch_bounds__(256) gate_kernel()
{
    __shared__ float red[256];
    for (int b = 0; b < Bb; b++) {
        const float* rl = g_rl + b * (SS - 1);
        const float* rr = g_rr + b * (SS - 1);
        float p = 0.f;
        for (int t = threadIdx.x; t <= SS - 4; t += 256) {
            float pr1 = 1.f / (1.f + expf(rl[t]     - rr[t + 1]));
            float pr0 = 1.f / (1.f + expf(rr[t + 2] - rl[t + 1]));
            float Pi  = sqrtf(pr1 * pr0 + 1e-9f);
            p += logf(Pi + 1e-8f);
        }
        red[threadIdx.x] = p;
        __syncthreads();
        for (int st = 128; st > 0; st >>= 1) {
            if (threadIdx.x < st) red[threadIdx.x] += red[threadIdx.x + st];
            __syncthreads();
        }
        if (threadIdx.x == 0) g_gate[b] = expf(red[0]);
        __syncthreads();
    }
    if (threadIdx.x == 0)
        g_skip = (g_gate[0] == 0.f && g_gate[1] == 0.f) ? 1 : 0;
}

// ---------------------------------------------------------------------------
// fp32 SIMT GEMM — safety path (QKV projections) + bias broadcast on skip.
// ---------------------------------------------------------------------------
#define GK 1024
#define GN 1024

__global__ void __launch_bounds__(256) sgemm128(
    const float* __restrict__ A, const float* __restrict__ Bm,
    const float* __restrict__ bias, float* __restrict__ C, int mode)
{
    const int n0 = blockIdx.x * 128;
    const int m0 = blockIdx.y * 128;
    const int tid = threadIdx.x;

    if (mode != 0 && g_skip) {
        if (mode == 2) {
            for (int idx = tid; idx < 128 * 32; idx += 256) {
                int r  = idx >> 5;
                int c4 = idx & 31;
                float4 bv = ((const float4*)(bias + n0))[c4];
                ((float4*)(C + (size_t)(m0 + r) * GN + n0))[c4] = bv;
            }
        }
        return;
    }

    __shared__ float As[8][128];
    __shared__ float Bs[8][128];

    float acc[8][8];
#pragma unroll
    for (int i = 0; i < 8; i++)
#pragma unroll
        for (int j = 0; j < 8; j++) acc[i][j] = 0.f;

    const int ty = tid >> 4;
    const int tx = tid & 15;
    const int arow = tid >> 1;
    const int acol = (tid & 1) * 4;
    const int brow = tid >> 5;
    const int bcol = (tid & 31) * 4;

    for (int k0 = 0; k0 < GK; k0 += 8) {
        float4 av = *(const float4*)(A + (size_t)(m0 + arow) * GK + k0 + acol);
        float4 bv = *(const float4*)(Bm + (size_t)(k0 + brow) * GN + n0 + bcol);
        As[acol + 0][arow] = av.x;
        As[acol + 1][arow] = av.y;
        As[acol + 2][arow] = av.z;
        As[acol + 3][arow] = av.w;
        *(float4*)&Bs[brow][bcol] = bv;
        __syncthreads();
#pragma unroll
        for (int kk = 0; kk < 8; kk++) {
            float a[8], bb[8];
            float4 a0 = *(const float4*)&As[kk][ty * 8];
            float4 a1 = *(const float4*)&As[kk][ty * 8 + 4];
            float4 b0 = *(const float4*)&Bs[kk][tx * 8];
            float4 b1 = *(const float4*)&Bs[kk][tx * 8 + 4];
            a[0]=a0.x; a[1]=a0.y; a[2]=a0.z; a[3]=a0.w;
            a[4]=a1.x; a[5]=a1.y; a[6]=a1.z; a[7]=a1.w;
            bb[0]=b0.x; bb[1]=b0.y; bb[2]=b0.z; bb[3]=b0.w;
            bb[4]=b1.x; bb[5]=b1.y; bb[6]=b1.z; bb[7]=b1.w;
#pragma unroll
            for (int i = 0; i < 8; i++)
#pragma unroll
                for (int j = 0; j < 8; j++) acc[i][j] += a[i] * bb[j];
        }
        __syncthreads();
    }

#pragma unroll
    for (int i = 0; i < 8; i++) {
        int m = m0 + ty * 8 + i;
#pragma unroll
        for (int j = 0; j < 8; j += 4) {
            int n = n0 + tx * 8 + j;
            float4 v;
            v.x = acc[i][j + 0] + (bias ? bias[n + 0] : 0.f);
            v.y = acc[i][j + 1] + (bias ? bias[n + 1] : 0.f);
            v.z = acc[i][j + 2] + (bias ? bias[n + 2] : 0.f);
            v.w = acc[i][j + 3] + (bias ? bias[n + 3] : 0.f);
            *(float4*)(C + (size_t)m * GN + n) = v;
        }
    }
}

// ---------------------------------------------------------------------------
// Flash-style causal attention (safety path; only runs if gate != 0).
// ---------------------------------------------------------------------------
#define KT 64
__global__ void __launch_bounds__(128) attention_kernel()
{
    if (g_skip) return;
    const int qt = blockIdx.x;
    const int bh = blockIdx.y;
    const int b = bh / HH, h = bh % HH;
    const int tid = threadIdx.x;
    const int q = qt * 128 + tid;

    const float* Qp = g_Q + ((size_t)b * SS + q) * DD + h * DKk;
    float qreg[DKk];
#pragma unroll
    for (int d = 0; d < DKk; d++) qreg[d] = Qp[d];

    float m = -CUDART_INF_F, l = 0.f;
    float accv[DKk];
#pragma unroll
    for (int d = 0; d < DKk; d++) accv[d] = 0.f;

    __shared__ float Ks[KT][DKk];
    __shared__ float Vs[KT][DKk];

    const int kmax = qt * 128 + 128;
    for (int k0 = 0; k0 < kmax; k0 += KT) {
        __syncthreads();
        for (int idx = tid; idx < KT * (DKk / 4); idx += 128) {
            int rr = idx / (DKk / 4), cc = idx % (DKk / 4);
            const float4* kp = (const float4*)(g_K + ((size_t)b * SS + k0 + rr) * DD + h * DKk) + cc;
            const float4* vp = (const float4*)(g_V + ((size_t)b * SS + k0 + rr) * DD + h * DKk) + cc;
            ((float4*)&Ks[rr][0])[cc] = *kp;
            ((float4*)&Vs[rr][0])[cc] = *vp;
        }
        __syncthreads();
        int jend = q - k0 + 1;
        if (jend > KT) jend = KT;
        for (int j = 0; j < jend; j++) {
            float s = 0.f;
#pragma unroll
            for (int d = 0; d < DKk; d++) s += qreg[d] * Ks[j][d];
            s *= 0.125f;
            float mn = fmaxf(m, s);
            float corr = __expf(m - mn);
            float pexp = __expf(s - mn);
            l = l * corr + pexp;
#pragma unroll
            for (int d = 0; d < DKk; d++) accv[d] = accv[d] * corr + pexp * Vs[j][d];
            m = mn;
        }
    }
    float inv = g_gate[b] / l;
    float* cp = g_ctx + ((size_t)b * SS + q) * DD + h * DKk;
#pragma unroll
    for (int d = 0; d < DKk; d++) cp[d] = accv[d] * inv;
}

// ---------------------------------------------------------------------------
// Launch
// ---------------------------------------------------------------------------
extern "C" void kernel_launch(void* const* d_in, const int* in_sizes, int n_in,
                              void* d_out, int out_size)
{
    const float* query = (const float*)d_in[0];
    const float* key   = (const float*)d_in[1];
    const float* value = (const float*)d_in[2];
    const float* Wq = (const float*)d_in[4];
    const float* bq = (const float*)d_in[5];
    const float* Wk = (const float*)d_in[6];
    const float* bk = (const float*)d_in[7];
    const float* Wv = (const float*)d_in[8];
    const float* bv = (const float*)d_in[9];
    const float* Wo = (const float*)d_in[10];
    const float* bo = (const float*)d_in[11];
    const float* Wp = (const float*)d_in[12];
    float* out = (float*)d_out;

    void *p_qbf, *p_wbf, *p_Q, *p_K, *p_V, *p_ctx;
    cudaGetSymbolAddress(&p_qbf, g_qbf);
    cudaGetSymbolAddress(&p_wbf, g_wbf);
    cudaGetSymbolAddress(&p_Q, g_Q);
    cudaGetSymbolAddress(&p_K, g_K);
    cudaGetSymbolAddress(&p_V, g_V);
    cudaGetSymbolAddress(&p_ctx, g_ctx);

    cudaFuncSetAttribute(gate_gemm_mma, cudaFuncAttributeMaxDynamicSharedMemorySize, SMEM_GEMM);

    dim3 gemm_grid(GN / 128, MM / 128);

    // 1) zero r accumulators
    zero_r_kernel<<<16, 256>>>();
    // 2) conversions for the tensor-core gate GEMM
    cvt_q_bf16<<<(MM * DD / 4) / 256, 256>>>((const float4*)query, (__nv_bfloat162*)p_qbf);
    cvt_w_bf16<<<(DD * DD / 4) / 256, 256>>>((const float4*)Wp, (__nv_bfloat162*)p_wbf);
    // 3) bf16 HMMA gate GEMM with fused r-dot epilogue
    gate_gemm_mma<<<dim3(DD / 128, MM / 128), 256, SMEM_GEMM>>>(key);
    // 4) gate + skip flag
    gate_kernel<<<1, 256>>>();
    // 5) QKV projections (skip if gate == 0)
    sgemm128<<<gemm_grid, 256>>>(query, Wq, bq, (float*)p_Q, 1);
    sgemm128<<<gemm_grid, 256>>>(key,   Wk, bk, (float*)p_K, 1);
    sgemm128<<<gemm_grid, 256>>>(value, Wv, bv, (float*)p_V, 1);
    // 6) causal attention * gate (skip if gate == 0)
    attention_kernel<<<dim3(SS / 128, Bb * HH), 128>>>();
    // 7) out = ctx @ Wo + bo, or bo broadcast on skip
    sgemm128<<<gemm_grid, 256>>>((const float*)p_ctx, Wo, bo, out, 2);
}

// round 6
// speedup vs baseline: 4.1668x; 1.0992x over previous
#include <cuda_runtime.h>
#include <cuda_bf16.h>
#include <math_constants.h>
#include <cstdint>

// Problem constants
#define Bb 2
#define SS 2048
#define DD 1024
#define HH 16
#define DKk 64
#define MM (Bb * SS)   // 4096 rows

// ---------------------------------------------------------------------------
// Scratch (device globals — no allocations allowed)
// ---------------------------------------------------------------------------
__device__ __nv_bfloat16 g_qbf[(size_t)MM * DD];      // query in bf16 (A, row-major)
__device__ __nv_bfloat16 g_wbf[(size_t)DD * DD];      // Wp in bf16 (B, row-major [k][n])
__device__ float g_Q[(size_t)Bb * SS * DD];
__device__ float g_K[(size_t)Bb * SS * DD];
__device__ float g_V[(size_t)Bb * SS * DD];
__device__ float g_ctx[(size_t)Bb * SS * DD];
__device__ float g_rl[Bb * (SS - 1)];
__device__ float g_rr[Bb * (SS - 1)];
__device__ float g_gate[Bb];
__device__ int   g_skip;

// ---------------------------------------------------------------------------
// mma.sync helpers (sm_80+ path — works on base sm_103 target)
// ---------------------------------------------------------------------------
__device__ __forceinline__ uint32_t smem_u32(const void* p) {
    uint32_t a;
    asm("{ .reg .u64 t; cvta.to.shared.u64 t, %1; cvt.u32.u64 %0, t; }" : "=r"(a) : "l"(p));
    return a;
}
__device__ __forceinline__ void cp16(uint32_t dst, const void* src) {
    asm volatile("cp.async.cg.shared.global [%0], [%1], 16;" :: "r"(dst), "l"(src));
}
__device__ __forceinline__ void ldm_x4(uint32_t& a0, uint32_t& a1, uint32_t& a2, uint32_t& a3,
                                       uint32_t addr) {
    asm volatile("ldmatrix.sync.aligned.m8n8.x4.shared.b16 {%0,%1,%2,%3}, [%4];"
                 : "=r"(a0), "=r"(a1), "=r"(a2), "=r"(a3) : "r"(addr));
}
__device__ __forceinline__ void ldm_x2t(uint32_t& b0, uint32_t& b1, uint32_t addr) {
    asm volatile("ldmatrix.sync.aligned.m8n8.x2.trans.shared.b16 {%0,%1}, [%2];"
                 : "=r"(b0), "=r"(b1) : "r"(addr));
}
__device__ __forceinline__ void mma16816(float* c, uint32_t a0, uint32_t a1, uint32_t a2,
                                         uint32_t a3, uint32_t b0, uint32_t b1) {
    asm volatile(
        "mma.sync.aligned.m16n8k16.row.col.f32.bf16.bf16.f32 "
        "{%0,%1,%2,%3}, {%4,%5,%6,%7}, {%8,%9}, {%0,%1,%2,%3};"
        : "+f"(c[0]), "+f"(c[1]), "+f"(c[2]), "+f"(c[3])
        : "r"(a0), "r"(a1), "r"(a2), "r"(a3), "r"(b0), "r"(b1));
}

// ---------------------------------------------------------------------------
// Gate GEMM (bf16 HMMA, 128x128 CTA tile, K-chunk 64, cp.async double buffer)
//   C[m,n] = sum_k q_bf16[m,k] * Wp_bf16[k,n]   (C never materialized)
// Fused epilogue:
//   r_left[b,s-1]  += C[m,:] . key[m-1,:]   (s>=1)
//   r_right[b,s]   += C[m,:] . key[m+1,:]   (s<=S-2)
// 2 CTAs/SM (occupancy was the round-5 bottleneck).
// ---------------------------------------------------------------------------
#define SMEM_GEMM (2 * 32768)   // double-buffered: A 16KB + B 16KB per buffer

__global__ void __launch_bounds__(256, 2) gate_gemm_mma(const float* __restrict__ key)
{
    extern __shared__ __align__(128) char sm[];
    const uint32_t sbase = smem_u32(sm);
    const int tid = threadIdx.x;
    const int lane = tid & 31;
    const int wid = tid >> 5;
    const int wm = wid >> 2;         // 0..1 : 64-row warp block
    const int wn = wid & 3;          // 0..3 : 32-col warp block
    const int n0 = blockIdx.x * 128;
    const int m0 = blockIdx.y * 128;

    float acc[4][4][4];
#pragma unroll
    for (int mi = 0; mi < 4; mi++)
#pragma unroll
        for (int ni = 0; ni < 4; ni++)
#pragma unroll
            for (int j = 0; j < 4; j++) acc[mi][ni][j] = 0.f;

    // chunk loader: A 128x64 bf16 (128B rows, xor-swizzled 16B chunks),
    //               B 64x128 bf16 (256B rows, xor-swizzled within 128B half)
    auto load_chunk = [&](int kc, int buf) {
        const uint32_t base = sbase + buf * 32768u;
#pragma unroll
        for (int p = 0; p < 4; p++) {
            int ra = (tid >> 3) + p * 32, ca = tid & 7;
            const char* src = (const char*)g_qbf +
                ((size_t)(m0 + ra) * DD + kc * 64 + ca * 8) * 2;
            cp16(base + ra * 128 + ((ca ^ (ra & 7)) << 4), src);
        }
#pragma unroll
        for (int p = 0; p < 4; p++) {
            int kb = (tid >> 4) + p * 16, cb = tid & 15;
            const char* src = (const char*)g_wbf +
                ((size_t)(kc * 64 + kb) * DD + n0 + cb * 8) * 2;
            uint32_t swc = (cb & 8) | ((cb ^ (kb & 7)) & 7);
            cp16(base + 16384 + kb * 256 + swc * 16, src);
        }
        asm volatile("cp.async.commit_group;" ::: "memory");
    };

    load_chunk(0, 0);
    for (int kc = 0; kc < 16; kc++) {
        const int buf = kc & 1;
        if (kc + 1 < 16) {
            load_chunk(kc + 1, buf ^ 1);
            asm volatile("cp.async.wait_group 1;" ::: "memory");
        } else {
            asm volatile("cp.async.wait_group 0;" ::: "memory");
        }
        __syncthreads();

        const uint32_t abase = sbase + buf * 32768u;
        const uint32_t bbase = abase + 16384u;
#pragma unroll
        for (int kk = 0; kk < 4; kk++) {
            uint32_t a[4][4];
#pragma unroll
            for (int mi = 0; mi < 4; mi++) {
                int r = wm * 64 + mi * 16 + (lane & 7) + ((lane >> 3) & 1) * 8;
                int c = kk * 2 + (lane >> 4);
                ldm_x4(a[mi][0], a[mi][1], a[mi][2], a[mi][3],
                       abase + r * 128 + ((c ^ (r & 7)) << 4));
            }
            uint32_t b[4][2];
#pragma unroll
            for (int ni = 0; ni < 4; ni++) {
                int k = kk * 16 + (lane & 15);
                int cc = wn * 4 + ni;
                uint32_t swc = (cc & 8) | ((cc ^ (k & 7)) & 7);
                ldm_x2t(b[ni][0], b[ni][1], bbase + k * 256 + swc * 16);
            }
#pragma unroll
            for (int mi = 0; mi < 4; mi++)
#pragma unroll
                for (int ni = 0; ni < 4; ni++)
                    mma16816(acc[mi][ni], a[mi][0], a[mi][1], a[mi][2], a[mi][3],
                             b[ni][0], b[ni][1]);
        }
        __syncthreads();
    }

    // Fused epilogue: r-dots straight off the fragments.
    // C frag map (m16n8k16): c0,c1 -> row q; c2,c3 -> row q+8; cols tq*2, tq*2+1.
    const int q = lane >> 2, tq = lane & 3;
#pragma unroll
    for (int mi = 0; mi < 4; mi++) {
        const int rbase = m0 + wm * 64 + mi * 16;
#pragma unroll
        for (int half = 0; half < 2; half++) {
            const int m = rbase + q + half * 8;
            const int s = m & (SS - 1);
            const int bI = m >> 11;
            const bool hasL = (s >= 1);
            const bool hasR = (s <= SS - 2);
            const float* kl = key + (size_t)(m - 1) * DD + n0 + wn * 32;
            const float* kr = key + (size_t)(m + 1) * DD + n0 + wn * 32;
            float dL = 0.f, dR = 0.f;
#pragma unroll
            for (int ni = 0; ni < 4; ni++) {
                float c0 = acc[mi][ni][half * 2 + 0];
                float c1 = acc[mi][ni][half * 2 + 1];
                int col = ni * 8 + tq * 2;
                if (hasL) { dL += c0 * kl[col] + c1 * kl[col + 1]; }
                if (hasR) { dR += c0 * kr[col] + c1 * kr[col + 1]; }
            }
            dL += __shfl_xor_sync(0xffffffffu, dL, 1);
            dL += __shfl_xor_sync(0xffffffffu, dL, 2);
            dR += __shfl_xor_sync(0xffffffffu, dR, 1);
            dR += __shfl_xor_sync(0xffffffffu, dR, 2);
            if (tq == 0) {
                if (hasL) atomicAdd(&g_rl[bI * (SS - 1) + (s - 1)], dL);
                if (hasR) atomicAdd(&g_rr[bI * (SS - 1) + s], dR);
            }
        }
    }
}

// ---------------------------------------------------------------------------
// Prep: zero r accumulators + convert query and Wp to bf16 — single launch.
// Blocks [0, QB4) handle query, [QB4, QB4+WB4) handle Wp.
// ---------------------------------------------------------------------------
#define QN4 (MM * DD / 4)   // 1,048,576 float4 groups
#define WN4 (DD * DD / 4)   //   262,144

__global__ void __launch_bounds__(256) prep_kernel(const float4* __restrict__ q,
                                                   const float4* __restrict__ w)
{
    const int i = blockIdx.x * 256 + threadIdx.x;
    if (i < Bb * (SS - 1)) { g_rl[i] = 0.f; g_rr[i] = 0.f; }
    if (i < QN4) {
        float4 v = q[i];
        ((__nv_bfloat162*)g_qbf)[2 * i]     = __floats2bfloat162_rn(v.x, v.y);
        ((__nv_bfloat162*)g_qbf)[2 * i + 1] = __floats2bfloat162_rn(v.z, v.w);
    } else {
        int j = i - QN4;
        float4 v = w[j];
        ((__nv_bfloat162*)g_wbf)[2 * j]     = __floats2bfloat162_rn(v.x, v.y);
        ((__nv_bfloat162*)g_wbf)[2 * j + 1] = __floats2bfloat162_rn(v.z, v.w);
    }
}

// ---------------------------------------------------------------------------
// Gate: softmax pairs -> Pi chain -> log-sum -> exp. Sets g_skip.
// ---------------------------------------------------------------------------
__global__ void __launch_bounds__(256) gate_kernel()
{
    __shared__ float red[256];
    for (int b = 0; b < Bb; b++) {
        const float* rl = g_rl + b * (SS - 1);
        const float* rr = g_rr + b * (SS - 1);
        float p = 0.f;
        for (int t = threadIdx.x; t <= SS - 4; t += 256) {
            float pr1 = 1.f / (1.f + expf(rl[t]     - rr[t + 1]));
            float pr0 = 1.f / (1.f + expf(rr[t + 2] - rl[t + 1]));
            float Pi  = sqrtf(pr1 * pr0 + 1e-9f);
            p += logf(Pi + 1e-8f);
        }
        red[threadIdx.x] = p;
        __syncthreads();
        for (int st = 128; st > 0; st >>= 1) {
            if (threadIdx.x < st) red[threadIdx.x] += red[threadIdx.x + st];
            __syncthreads();
        }
        if (threadIdx.x == 0) g_gate[b] = expf(red[0]);
        __syncthreads();
    }
    if (threadIdx.x == 0)
        g_skip = (g_gate[0] == 0.f && g_gate[1] == 0.f) ? 1 : 0;
}

// ---------------------------------------------------------------------------
// fp32 SIMT GEMM body (safety path) — shared by QKV (merged) and output proj.
// ---------------------------------------------------------------------------
#define GK 1024
#define GN 1024

__device__ __forceinline__ void sgemm_body(
    const float* __restrict__ A, const float* __restrict__ Bm,
    const float* __restrict__ bias, float* __restrict__ C, int m0, int n0, int tid)
{
    __shared__ float As[8][128];
    __shared__ float Bs[8][128];

    float acc[8][8];
#pragma unroll
    for (int i = 0; i < 8; i++)
#pragma unroll
        for (int j = 0; j < 8; j++) acc[i][j] = 0.f;

    const int ty = tid >> 4;
    const int tx = tid & 15;
    const int arow = tid >> 1;
    const int acol = (tid & 1) * 4;
    const int brow = tid >> 5;
    const int bcol = (tid & 31) * 4;

    for (int k0 = 0; k0 < GK; k0 += 8) {
        float4 av = *(const float4*)(A + (size_t)(m0 + arow) * GK + k0 + acol);
        float4 bv = *(const float4*)(Bm + (size_t)(k0 + brow) * GN + n0 + bcol);
        As[acol + 0][arow] = av.x;
        As[acol + 1][arow] = av.y;
        As[acol + 2][arow] = av.z;
        As[acol + 3][arow] = av.w;
        *(float4*)&Bs[brow][bcol] = bv;
        __syncthreads();
#pragma unroll
        for (int kk = 0; kk < 8; kk++) {
            float a[8], bb[8];
            float4 a0 = *(const float4*)&As[kk][ty * 8];
            float4 a1 = *(const float4*)&As[kk][ty * 8 + 4];
            float4 b0 = *(const float4*)&Bs[kk][tx * 8];
            float4 b1 = *(const float4*)&Bs[kk][tx * 8 + 4];
            a[0]=a0.x; a[1]=a0.y; a[2]=a0.z; a[3]=a0.w;
            a[4]=a1.x; a[5]=a1.y; a[6]=a1.z; a[7]=a1.w;
            bb[0]=b0.x; bb[1]=b0.y; bb[2]=b0.z; bb[3]=b0.w;
            bb[4]=b1.x; bb[5]=b1.y; bb[6]=b1.z; bb[7]=b1.w;
#pragma unroll
            for (int i = 0; i < 8; i++)
#pragma unroll
                for (int j = 0; j < 8; j++) acc[i][j] += a[i] * bb[j];
        }
        __syncthreads();
    }

#pragma unroll
    for (int i = 0; i < 8; i++) {
        int m = m0 + ty * 8 + i;
#pragma unroll
        for (int j = 0; j < 8; j += 4) {
            int n = n0 + tx * 8 + j;
            float4 v;
            v.x = acc[i][j + 0] + bias[n + 0];
            v.y = acc[i][j + 1] + bias[n + 1];
            v.z = acc[i][j + 2] + bias[n + 2];
            v.w = acc[i][j + 3] + bias[n + 3];
            *(float4*)(C + (size_t)m * GN + n) = v;
        }
    }
}

// Merged QKV projections (one launch; z selects operand set). Skipped when gate==0.
__global__ void __launch_bounds__(256) sgemm_qkv(
    const float* __restrict__ q, const float* __restrict__ k, const float* __restrict__ v,
    const float* __restrict__ Wq, const float* __restrict__ bq,
    const float* __restrict__ Wk, const float* __restrict__ bk,
    const float* __restrict__ Wv, const float* __restrict__ bv)
{
    if (g_skip) return;
    const float* A; const float* W; const float* bias; float* C;
    if (blockIdx.z == 0)      { A = q; W = Wq; bias = bq; C = g_Q; }
    else if (blockIdx.z == 1) { A = k; W = Wk; bias = bk; C = g_K; }
    else                      { A = v; W = Wv; bias = bv; C = g_V; }
    sgemm_body(A, W, bias, C, blockIdx.y * 128, blockIdx.x * 128, threadIdx.x);
}

// Output projection; on skip writes the exact reference result (bo broadcast).
__global__ void __launch_bounds__(256) sgemm_out(const float* __restrict__ bias,
                                                 const float* __restrict__ Wo,
                                                 float* __restrict__ C)
{
    const int n0 = blockIdx.x * 128;
    const int m0 = blockIdx.y * 128;
    const int tid = threadIdx.x;
    if (g_skip) {
        for (int idx = tid; idx < 128 * 32; idx += 256) {
            int r  = idx >> 5;
            int c4 = idx & 31;
            float4 bv = ((const float4*)(bias + n0))[c4];
            ((float4*)(C + (size_t)(m0 + r) * GN + n0))[c4] = bv;
        }
        return;
    }
    sgemm_body(g_ctx, Wo, bias, C, m0, n0, tid);
}

// ---------------------------------------------------------------------------
// Flash-style causal attention (safety path; only runs if gate != 0).
// ---------------------------------------------------------------------------
#define KT 64
__global__ void __launch_bounds__(128) attention_kernel()
{
    if (g_skip) return;
    const int qt = blockIdx.x;
    const int bh = blockIdx.y;
    const int b = bh / HH, h = bh % HH;
    const int tid = threadIdx.x;
    const int q = qt * 128 + tid;

    const float* Qp = g_Q + ((size_t)b * SS + q) * DD + h * DKk;
    float qreg[DKk];
#pragma unroll
    for (int d = 0; d < DKk; d++) qreg[d] = Qp[d];

    float m = -CUDART_INF_F, l = 0.f;
    float accv[DKk];
#pragma unroll
    for (int d = 0; d < DKk; d++) accv[d] = 0.f;

    __shared__ float Ks[KT][DKk];
    __shared__ float Vs[KT][DKk];

    const int kmax = qt * 128 + 128;
    for (int k0 = 0; k0 < kmax; k0 += KT) {
        __syncthreads();
        for (int idx = tid; idx < KT * (DKk / 4); idx += 128) {
            int rr = idx / (DKk / 4), cc = idx % (DKk / 4);
            const float4* kp = (const float4*)(g_K + ((size_t)b * SS + k0 + rr) * DD + h * DKk) + cc;
            const float4* vp = (const float4*)(g_V + ((size_t)b * SS + k0 + rr) * DD + h * DKk) + cc;
            ((float4*)&Ks[rr][0])[cc] = *kp;
            ((float4*)&Vs[rr][0])[cc] = *vp;
        }
        __syncthreads();
        int jend = q - k0 + 1;
        if (jend > KT) jend = KT;
        for (int j = 0; j < jend; j++) {
            float s = 0.f;
#pragma unroll
            for (int d = 0; d < DKk; d++) s += qreg[d] * Ks[j][d];
            s *= 0.125f;
            float mn = fmaxf(m, s);
            float corr = __expf(m - mn);
            float pexp = __expf(s - mn);
            l = l * corr + pexp;
#pragma unroll
            for (int d = 0; d < DKk; d++) accv[d] = accv[d] * corr + pexp * Vs[j][d];
            m = mn;
        }
    }
    float inv = g_gate[b] / l;
    float* cp = g_ctx + ((size_t)b * SS + q) * DD + h * DKk;
#pragma unroll
    for (int d = 0; d < DKk; d++) cp[d] = accv[d] * inv;
}

// ---------------------------------------------------------------------------
// Launch
// ---------------------------------------------------------------------------
extern "C" void kernel_launch(void* const* d_in, const int* in_sizes, int n_in,
                              void* d_out, int out_size)
{
    const float* query = (const float*)d_in[0];
    const float* key   = (const float*)d_in[1];
    const float* value = (const float*)d_in[2];
    const float* Wq = (const float*)d_in[4];
    const float* bq = (const float*)d_in[5];
    const float* Wk = (const float*)d_in[6];
    const float* bk = (const float*)d_in[7];
    const float* Wv = (const float*)d_in[8];
    const float* bv = (const float*)d_in[9];
    const float* Wo = (const float*)d_in[10];
    const float* bo = (const float*)d_in[11];
    const float* Wp = (const float*)d_in[12];
    float* out = (float*)d_out;

    cudaFuncSetAttribute(gate_gemm_mma, cudaFuncAttributeMaxDynamicSharedMemorySize, SMEM_GEMM);

    // 1) prep: zero r + both bf16 conversions (one launch)
    prep_kernel<<<(QN4 + WN4) / 256, 256>>>((const float4*)query, (const float4*)Wp);
    // 2) bf16 HMMA gate GEMM with fused r-dot epilogue (2 CTAs/SM)
    gate_gemm_mma<<<dim3(DD / 128, MM / 128), 256, SMEM_GEMM>>>(key);
    // 3) gate + skip flag
    gate_kernel<<<1, 256>>>();
    // 4) QKV projections — single launch, skipped when gate == 0
    sgemm_qkv<<<dim3(GN / 128, MM / 128, 3), 256>>>(query, key, value,
                                                    Wq, bq, Wk, bk, Wv, bv);
    // 5) causal attention * gate (skip if gate == 0)
    attention_kernel<<<dim3(SS / 128, Bb * HH), 128>>>();
    // 6) out = ctx @ Wo + bo, or bo broadcast on skip
    sgemm_out<<<dim3(GN / 128, MM / 128), 256>>>(bo, Wo, out);
}